// round 1
// baseline (speedup 1.0000x reference)
#include <cuda_runtime.h>

// Problem constants
// v: [8][1024][8][64] f32, w: [1][8][63] f32, out: [8][1024][8][64] f32
// s = 32, L = 1024, HD = 8*64 = 512 "columns" per (n, l)

#define NB    8      // batch
#define S     32     // sqrt(seq)
#define HD    512    // h*d columns
#define HD4   128    // HD / 4

// Scratch: 4 x 512 KB = 2 MB of __device__ globals (allowed; no allocation)
__device__ float4 g_R[NB * S * HD4];  // R[n][c][hd]
__device__ float4 g_C[NB * S * HD4];  // C[n][e][hd]
__device__ float4 g_A[NB * S * HD4];  // A[n][a][hd]
__device__ float4 g_B[NB * S * HD4];  // B[n][b][hd]

// ---------------------------------------------------------------------------
// Kernel 1: partial row/col sums over the 32x32 sequence grid.
//   R[n,c,hd] = sum_e v[n, c*32+e, hd]   (contiguous 64KB chunk per block)
//   C[n,e,hd] = sum_c v[n, c*32+e, hd]   (rows strided by 32*HD)
// grid = 512 (256 R-blocks + 256 C-blocks), 128 threads (float4 per thread)
// ---------------------------------------------------------------------------
__global__ void rc_kernel(const float4* __restrict__ v4) {
    int bid = blockIdx.x;
    bool isC = bid >= 256;
    int nb = bid & 255;
    int n = nb >> 5;
    int k = nb & 31;          // c for R-blocks, e for C-blocks
    int t = threadIdx.x;      // float4 column 0..127

    const float4* base = v4 + (size_t)n * 1024 * HD4;
    float4 acc = make_float4(0.f, 0.f, 0.f, 0.f);

    if (!isC) {
        // rows l = k*32 + e, e = 0..31  (contiguous block of rows)
        const float4* p = base + (size_t)(k * 32) * HD4 + t;
        #pragma unroll
        for (int e = 0; e < 32; ++e) {
            float4 x = p[e * HD4];
            acc.x += x.x; acc.y += x.y; acc.z += x.z; acc.w += x.w;
        }
        g_R[(n * S + k) * HD4 + t] = acc;
    } else {
        // rows l = c*32 + k, c = 0..31  (stride 32 rows)
        const float4* p = base + (size_t)k * HD4 + t;
        #pragma unroll
        for (int c = 0; c < 32; ++c) {
            float4 x = p[c * 32 * HD4];
            acc.x += x.x; acc.y += x.y; acc.z += x.z; acc.w += x.w;
        }
        g_C[(n * S + k) * HD4 + t] = acc;
    }
}

// ---------------------------------------------------------------------------
// Kernel 2: A[n,j,hd] = sum_k bias[h,j,k] * R[n,k,hd]   (which = 0)
//           B[n,j,hd] = sum_k bias[h,j,k] * C[n,k,hd]   (which = 1)
// bias[h,j,k] = w[h*63 + (32 - k + j) mod 63]
// grid = 128 (which:2 x n:8 x h:8), 64 threads (one d each)
// ---------------------------------------------------------------------------
__global__ void ab_kernel(const float* __restrict__ w) {
    int bid   = blockIdx.x;
    int which = bid >> 6;          // 0: R->A, 1: C->B
    int n     = (bid >> 3) & 7;
    int h     = bid & 7;
    int d     = threadIdx.x;       // 0..63

    __shared__ float sb[32][33];   // bias[j][k] for this h (pad avoids conflicts)
    for (int idx = d; idx < 1024; idx += 64) {
        int j = idx >> 5, k = idx & 31;
        sb[j][k] = w[h * 63 + ((32 - k + j) % 63)];
    }

    const float* src = which ? (const float*)g_C : (const float*)g_R;
    float r[32];
    #pragma unroll
    for (int k = 0; k < 32; ++k)
        r[k] = src[(n * S + k) * HD + h * 64 + d];

    __syncthreads();

    float* dst = which ? (float*)g_B : (float*)g_A;
    #pragma unroll
    for (int j = 0; j < 32; ++j) {
        float acc = 0.f;
        #pragma unroll
        for (int k = 0; k < 32; ++k)
            acc = fmaf(sb[j][k], r[k], acc);
        dst[(n * S + j) * HD + h * 64 + d] = acc;
    }
}

// ---------------------------------------------------------------------------
// Kernel 3: out[n, a*32+b, h, d] = A[n,a,hd] + B[n,b,hd]
// 1M float4 threads; A row reused across 32 b's, B slice (64KB) L1-resident.
// grid = 4096 x 256
// ---------------------------------------------------------------------------
__global__ void out_kernel(float4* __restrict__ out4) {
    int g = blockIdx.x * 256 + threadIdx.x;      // 0 .. 2^20-1
    int d4 = g & 15;
    int h  = (g >> 4) & 7;
    int j  = (g >> 7) & 1023;
    int n  = g >> 17;
    int a  = j >> 5;
    int b  = j & 31;
    int col4 = h * 16 + d4;

    float4 x = g_A[(n * S + a) * HD4 + col4];
    float4 y = g_B[(n * S + b) * HD4 + col4];
    x.x += y.x; x.y += y.y; x.z += y.z; x.w += y.w;
    out4[g] = x;
}

extern "C" void kernel_launch(void* const* d_in, const int* in_sizes, int n_in,
                              void* d_out, int out_size) {
    const float* v = (const float*)d_in[0];
    const float* w = (const float*)d_in[1];
    // Defensive: v has 4,194,304 elements, w has 504.
    if (n_in >= 2 && in_sizes[0] < in_sizes[1]) {
        const float* tmp = v; v = w; w = tmp;
    }

    rc_kernel<<<512, 128>>>((const float4*)v);
    ab_kernel<<<128, 64>>>(w);
    out_kernel<<<4096, 256>>>((float4*)d_out);
}

// round 2
// speedup vs baseline: 1.1530x; 1.1530x over previous
#include <cuda_runtime.h>

// v: [8][1024][8][64] f32, w: [1][8][63] f32, out: [8][1024][8][64] f32
// Factorization (s=32, j = a*32+b, l = c*32+e):
//   out[n,j,hd] = A[n,a,hd] + B[n,b,hd]
//   A = bias @ R,  B = bias @ C,  R[c]=sum_e v[c*32+e], C[e]=sum_c v[c*32+e]
//   bias[h,j,k] = w[h, (32 - k + j) mod 63]

#define NB   8
#define S    32
#define HD   512
#define HD4  128

__device__ float4 g_R[NB * S * HD4];  // 512 KB
__device__ float4 g_C[NB * S * HD4];  // 512 KB

// ---------------------------------------------------------------------------
// Kernel 1: R and C partial sums. grid=512 (256 R + 256 C), block=512.
// Each block: one (n,k); 4 row-groups of 8 rows per warp-group, smem combine.
// ---------------------------------------------------------------------------
__global__ void rc_kernel(const float4* __restrict__ v4) {
    int bid = blockIdx.x;
    bool isC = bid >= 256;
    int nb = bid & 255;
    int n = nb >> 5;
    int k = nb & 31;             // c for R, e for C
    int t = threadIdx.x;
    int col = t & 127;           // float4 column
    int rg = t >> 7;             // row group 0..3

    const float4* base = v4 + (size_t)n * 1024 * HD4;
    float4 acc = make_float4(0.f, 0.f, 0.f, 0.f);

    if (!isC) {
        // rows l = k*32 + (rg*8 + i): contiguous
        const float4* p = base + (size_t)(k * 32 + rg * 8) * HD4 + col;
        #pragma unroll
        for (int i = 0; i < 8; ++i) {
            float4 x = p[i * HD4];
            acc.x += x.x; acc.y += x.y; acc.z += x.z; acc.w += x.w;
        }
    } else {
        // rows l = (rg*8 + i)*32 + k: stride 32 rows
        const float4* p = base + (size_t)(rg * 8 * 32 + k) * HD4 + col;
        #pragma unroll
        for (int i = 0; i < 8; ++i) {
            float4 x = p[i * 32 * HD4];
            acc.x += x.x; acc.y += x.y; acc.z += x.z; acc.w += x.w;
        }
    }

    __shared__ float4 s[512];
    s[t] = acc;
    __syncthreads();

    if (rg == 0) {
        float4 a = s[col], b = s[col + 128], c = s[col + 256], d = s[col + 384];
        float4 r;
        r.x = (a.x + b.x) + (c.x + d.x);
        r.y = (a.y + b.y) + (c.y + d.y);
        r.z = (a.z + b.z) + (c.z + d.z);
        r.w = (a.w + b.w) + (c.w + d.w);
        (isC ? g_C : g_R)[(n * S + k) * HD4 + col] = r;
    }
}

// ---------------------------------------------------------------------------
// Kernel 2 (fused ab + out): block = (n, h, quarter-of-j), grid=256, block=256.
// Computes A,B for this (n,h) into smem, writes its 256-j output quarter.
// ---------------------------------------------------------------------------
__global__ void abo_kernel(const float* __restrict__ w, float4* __restrict__ out4) {
    int blk = blockIdx.x;
    int q = blk & 3;             // j quarter
    int h = (blk >> 2) & 7;
    int n = blk >> 5;
    int tid = threadIdx.x;       // 256

    __shared__ float sb[32][33];        // bias[j][k], padded
    __shared__ float sR[32][64];        // R[k][d] for this (n,h)
    __shared__ float sC[32][64];
    __shared__ float sA[32][64];
    __shared__ float sB[32][64];

    // bias
    for (int idx = tid; idx < 1024; idx += 256) {
        int j = idx >> 5, k = idx & 31;
        sb[j][k] = w[h * 63 + ((32 - k + j) % 63)];
    }
    // R, C slices: 32 k x 16 float4 each
    for (int idx = tid; idx < 512; idx += 256) {
        int k = idx >> 4, d4 = idx & 15;
        float4 r = g_R[(n * S + k) * HD4 + h * 16 + d4];
        float4 c = g_C[(n * S + k) * HD4 + h * 16 + d4];
        reinterpret_cast<float4*>(&sR[k][0])[d4] = r;
        reinterpret_cast<float4*>(&sC[k][0])[d4] = c;
    }
    __syncthreads();

    // A[a][d] = sum_k sb[a][k]*sR[k][d];  B likewise with sC. 8 (a,d) items/thread.
    {
        int d = tid & 63;
        int a0 = tid >> 6;       // 0..3
        #pragma unroll
        for (int ai = 0; ai < 8; ++ai) {
            int a = a0 + ai * 4;
            float accA = 0.f, accB = 0.f;
            #pragma unroll
            for (int k = 0; k < 32; ++k) {
                float bw = sb[a][k];
                accA = fmaf(bw, sR[k][d], accA);
                accB = fmaf(bw, sC[k][d], accB);
            }
            sA[a][d] = accA;
            sB[a][d] = accB;
        }
    }
    __syncthreads();

    // Write quarter q: j in [q*256, q*256+256). 16 float4 stores per thread.
    int d4 = tid & 15;
    int jrow = tid >> 4;         // 0..15
    #pragma unroll
    for (int it = 0; it < 16; ++it) {
        int j = q * 256 + it * 16 + jrow;
        int a = j >> 5, b = j & 31;
        float4 x = reinterpret_cast<float4*>(&sA[a][0])[d4];
        float4 y = reinterpret_cast<float4*>(&sB[b][0])[d4];
        x.x += y.x; x.y += y.y; x.z += y.z; x.w += y.w;
        out4[(size_t)(n * 1024 + j) * HD4 + h * 16 + d4] = x;
    }
}

extern "C" void kernel_launch(void* const* d_in, const int* in_sizes, int n_in,
                              void* d_out, int out_size) {
    const float* v = (const float*)d_in[0];
    const float* w = (const float*)d_in[1];
    if (n_in >= 2 && in_sizes[0] < in_sizes[1]) {
        const float* tmp = v; v = w; w = tmp;
    }

    rc_kernel<<<512, 512>>>((const float4*)v);
    abo_kernel<<<256, 256>>>(w, (float4*)d_out);
}